// round 3
// baseline (speedup 1.0000x reference)
#include <cuda_runtime.h>
#include <cuda_bf16.h>
#include <cstdint>

// DIN sequence encoder, B=4096, L=200, E=A=128.
// Factorization: att_in@W1 = q@(W1a+W1c) + keys_p@[(W1b-W1c) + diag(q)*W1d]
// One CTA per batch row. fp32 with packed fma.rn.f32x2 (sm_103a).
// 8x8 register tiles, 128-row l-tiles -> FMA-pipe bound.

#define EB 128
#define AB 128
#define LK 200
#define NB 4096
#define STRK 132                 // Kt/H1 row stride in floats (16B-aligned, low conflict)

__device__ float g_W1k[EB * AB];     // W1b - W1c
__device__ float g_U[NB * AB];       // per-batch u = q @ (W1a+W1c) + b1
__device__ int   g_len64;            // 1 if keys_length is int64

// ---------------- prep kernel: grid 129 x 256, dyn smem 16512 floats ----------------
// blocks 0..63 : g_W1k
// block  64    : keys_length dtype sniffer
// blocks 65..128: g_U for 64 batches each
__global__ void prep_kernel(const float* __restrict__ W1,
                            const float* __restrict__ b1,
                            const float* __restrict__ query,
                            const unsigned int* __restrict__ kl_words, int B) {
    extern __shared__ float sp[];           // 16384 (W1q) + 128 (q)
    const int t = threadIdx.x;
    const int blk = blockIdx.x;

    if (blk < 64) {
        int i = blk * 256 + t;
        g_W1k[i] = W1[EB * AB + i] - W1[2 * EB * AB + i];
        return;
    }
    if (blk == 64) {
        // int64 lengths in [1,200] -> every odd 32-bit word of first B words is 0
        int local = 0;
        for (int i = t; i < B / 2; i += 256)
            if (kl_words[2 * i + 1] != 0u) local = 1;
        int any = __syncthreads_or(local);
        if (t == 0) g_len64 = any ? 0 : 1;
        return;
    }

    // U blocks
    float* sW = sp;            // 16384: W1a + W1c
    float* sq = sp + 16384;    // 128
    for (int i = t; i < EB * AB; i += 256)
        sW[i] = W1[i] + W1[2 * EB * AB + i];
    __syncthreads();

    int bid2 = blk - 65;       // 0..63
    for (int bb2 = 0; bb2 < 64; bb2++) {
        int bb = bid2 * 64 + bb2;
        if (t < 128) sq[t] = query[(size_t)bb * EB + t];
        __syncthreads();
        if (t < 128) {
            float acc = b1[t];
            #pragma unroll 8
            for (int e = 0; e < EB; e++) acc += sq[e] * sW[e * AB + t];
            g_U[(size_t)bb * AB + t] = acc;
        }
        __syncthreads();
    }
}

// ---------------- f32x2 helpers ----------------
__device__ __forceinline__ unsigned long long packdup(float x) {
    unsigned long long r;
    asm("mov.b64 %0, {%1,%1};" : "=l"(r) : "f"(x));
    return r;
}
__device__ __forceinline__ void unpack2(unsigned long long v, float& lo, float& hi) {
    asm("mov.b64 {%0,%1}, %2;" : "=f"(lo), "=f"(hi) : "l"(v));
}
__device__ __forceinline__ void fma2(unsigned long long& d, unsigned long long a, unsigned long long b) {
    asm("fma.rn.f32x2 %0, %1, %2, %0;" : "+l"(d) : "l"(a), "l"(b));
}

// ---------------- SMEM layout (floats) ----------------
#define OFF_WB   0                        // 16384
#define OFF_W2   16384                    // 16384
#define OFF_KH   32768                    // 128*132 = 16896 (Kt then H1, reused)
#define OFF_Q    49664                    // 128
#define OFF_U    49792                    // 128
#define OFF_B2   49920                    // 128
#define OFF_W3   50048                    // 128
#define OFF_SC   50176                    // 256
#define OFF_RED  50432                    // 256
#define SMEM_FLOATS 50688
#define SMEM_BYTES  (SMEM_FLOATS * 4)

__global__ void __launch_bounds__(256, 1) din_kernel(
    const float* __restrict__ query,
    const float* __restrict__ keys,
    const void*  __restrict__ keys_length,
    const float* __restrict__ pos_emb,
    const float* __restrict__ W1,
    const float* __restrict__ b2,
    const float* __restrict__ W2,
    const float* __restrict__ W3,
    const float* __restrict__ b3,
    float* __restrict__ out)
{
    extern __shared__ float sm[];
    float* sWb  = sm + OFF_WB;
    float* sW2  = sm + OFF_W2;
    float* sKH  = sm + OFF_KH;
    float* sQ   = sm + OFF_Q;
    float* sU   = sm + OFF_U;
    float* sB2  = sm + OFF_B2;
    float* sW3  = sm + OFF_W3;
    float* sSc  = sm + OFF_SC;
    float* sRed = sm + OFF_RED;

    const int b = blockIdx.x;
    const int t = threadIdx.x;

    // ---- setup ----
    if (t < 128) {
        sQ[t]  = query[(size_t)b * EB + t];
        sU[t]  = g_U[(size_t)b * AB + t];
        sB2[t] = b2[t];
        sW3[t] = W3[t];
    }
    __syncthreads();

    const float* W1d = W1 + 3 * EB * AB;
    #pragma unroll 4
    for (int i = t; i < EB * AB; i += 256) {
        int e = i >> 7;
        sWb[i] = g_W1k[i] + sQ[e] * W1d[i];
        sW2[i] = W2[i];
    }
    const float b3v = b3[0];
    __syncthreads();

    // thread tiling: 8 l-rows x 8 a-cols per thread
    const int lt = t >> 4;            // 0..15 -> rows lb..lb+7
    const int at = t & 15;            // 0..15
    const int lb = lt * 8;
    const int c0 = 4 * at;            // cols c0..c0+3
    const int c1 = 64 + 4 * at;       // cols c1..c1+3

    for (int tile = 0; tile < 2; tile++) {
        const int l0 = tile * 128;

        // ---- stage keys_p tile transposed: sKH[e*STRK + l] ----
        #pragma unroll 4
        for (int idx = t; idx < 128 * EB; idx += 256) {
            int l = idx >> 7, e = idx & 127;
            int gl = l0 + l;
            float v = 0.0f;
            if (gl < LK)
                v = keys[((size_t)b * LK + gl) * EB + e] + pos_emb[gl * EB + e];
            sKH[e * STRK + l] = v;
        }
        __syncthreads();

        // ---- GEMM1: z1[l,a] = keys_p @ Wb ----
        unsigned long long acc[8][4];
        #pragma unroll
        for (int j = 0; j < 8; j++)
            #pragma unroll
            for (int k = 0; k < 4; k++) acc[j][k] = 0ULL;

        #pragma unroll 2
        for (int e = 0; e < EB; e++) {
            float4 a0 = *(const float4*)(sKH + e * STRK + lb);
            float4 a1 = *(const float4*)(sKH + e * STRK + lb + 4);
            ulonglong2 bv0 = *(const ulonglong2*)(sWb + e * AB + c0);
            ulonglong2 bv1 = *(const ulonglong2*)(sWb + e * AB + c1);
            unsigned long long d[8];
            d[0] = packdup(a0.x); d[1] = packdup(a0.y);
            d[2] = packdup(a0.z); d[3] = packdup(a0.w);
            d[4] = packdup(a1.x); d[5] = packdup(a1.y);
            d[6] = packdup(a1.z); d[7] = packdup(a1.w);
            #pragma unroll
            for (int j = 0; j < 8; j++) {
                fma2(acc[j][0], d[j], bv0.x);
                fma2(acc[j][1], d[j], bv0.y);
                fma2(acc[j][2], d[j], bv1.x);
                fma2(acc[j][3], d[j], bv1.y);
            }
        }
        __syncthreads();   // all Kt reads done -> safe to overwrite with H1

        // ---- epilogue 1: H1[col][l] = relu(z1 + u[col]) into sKH ----
        #pragma unroll
        for (int kk = 0; kk < 4; kk++) {
            int colL = (kk < 2) ? (c0 + 2 * kk) : (c1 + 2 * (kk - 2));
            int colH = colL + 1;
            float uL = sU[colL], uH = sU[colH];
            float loA[8], hiA[8];
            #pragma unroll
            for (int j = 0; j < 8; j++) {
                float lo, hi;
                unpack2(acc[j][kk], lo, hi);
                loA[j] = fmaxf(lo + uL, 0.0f);
                hiA[j] = fmaxf(hi + uH, 0.0f);
            }
            *(float4*)(sKH + colL * STRK + lb)     = make_float4(loA[0], loA[1], loA[2], loA[3]);
            *(float4*)(sKH + colL * STRK + lb + 4) = make_float4(loA[4], loA[5], loA[6], loA[7]);
            *(float4*)(sKH + colH * STRK + lb)     = make_float4(hiA[0], hiA[1], hiA[2], hiA[3]);
            *(float4*)(sKH + colH * STRK + lb + 4) = make_float4(hiA[4], hiA[5], hiA[6], hiA[7]);
        }
        __syncthreads();

        // ---- GEMM2: z2[l,a] = H1 @ W2 ----
        #pragma unroll
        for (int j = 0; j < 8; j++)
            #pragma unroll
            for (int k = 0; k < 4; k++) acc[j][k] = 0ULL;

        #pragma unroll 2
        for (int e = 0; e < AB; e++) {
            float4 a0 = *(const float4*)(sKH + e * STRK + lb);
            float4 a1 = *(const float4*)(sKH + e * STRK + lb + 4);
            ulonglong2 bv0 = *(const ulonglong2*)(sW2 + e * AB + c0);
            ulonglong2 bv1 = *(const ulonglong2*)(sW2 + e * AB + c1);
            unsigned long long d[8];
            d[0] = packdup(a0.x); d[1] = packdup(a0.y);
            d[2] = packdup(a0.z); d[3] = packdup(a0.w);
            d[4] = packdup(a1.x); d[5] = packdup(a1.y);
            d[6] = packdup(a1.z); d[7] = packdup(a1.w);
            #pragma unroll
            for (int j = 0; j < 8; j++) {
                fma2(acc[j][0], d[j], bv0.x);
                fma2(acc[j][1], d[j], bv0.y);
                fma2(acc[j][2], d[j], bv1.x);
                fma2(acc[j][3], d[j], bv1.y);
            }
        }

        // ---- epilogue 2: scores = sum_col relu(z2 + b2)*w3 ----
        {
            float sc[8] = {0,0,0,0,0,0,0,0};
            #pragma unroll
            for (int kk = 0; kk < 4; kk++) {
                int colL = (kk < 2) ? (c0 + 2 * kk) : (c1 + 2 * (kk - 2));
                int colH = colL + 1;
                float bL = sB2[colL], bH = sB2[colH];
                float wL = sW3[colL], wH = sW3[colH];
                #pragma unroll
                for (int j = 0; j < 8; j++) {
                    float lo, hi;
                    unpack2(acc[j][kk], lo, hi);
                    sc[j] += fmaxf(lo + bL, 0.0f) * wL + fmaxf(hi + bH, 0.0f) * wH;
                }
            }
            #pragma unroll
            for (int off = 8; off > 0; off >>= 1)
                #pragma unroll
                for (int j = 0; j < 8; j++)
                    sc[j] += __shfl_down_sync(0xffffffffu, sc[j], off, 16);
            if (at == 0) {
                #pragma unroll
                for (int j = 0; j < 8; j++)
                    sSc[l0 + lb + j] = sc[j] + b3v;
            }
        }
        __syncthreads();   // H1 reads done; scores visible; safe to restage
    }

    // ---- softmax over valid l ----
    int kli;
    if (g_len64) kli = (int)((const long long*)keys_length)[b];
    else         kli = ((const int*)keys_length)[b];
    kli = min(max(kli, 0), LK);

    const int wid = t >> 5, lane = t & 31;
    float s = (t < kli) ? sSc[t] : -3.0e38f;
    float mw = s;
    #pragma unroll
    for (int off = 16; off > 0; off >>= 1)
        mw = fmaxf(mw, __shfl_down_sync(0xffffffffu, mw, off));
    if (lane == 0) sRed[wid] = mw;
    __syncthreads();
    float m = sRed[0];
    #pragma unroll
    for (int w = 1; w < 8; w++) m = fmaxf(m, sRed[w]);

    float wgt = (t < kli) ? expf(s - m) : 0.0f;
    sSc[t] = wgt;
    float sw = wgt;
    #pragma unroll
    for (int off = 16; off > 0; off >>= 1)
        sw += __shfl_down_sync(0xffffffffu, sw, off);
    if (lane == 0) sRed[8 + wid] = sw;
    __syncthreads();
    float tot = 0.0f;
    #pragma unroll
    for (int w = 0; w < 8; w++) tot += sRed[8 + w];
    const float inv = 1.0f / tot;
    __syncthreads();

    // ---- weighted sum of keys_p ----
    {
        int ei = t & 127, half = t >> 7;
        float acc = 0.0f;
        const float* kb = keys + (size_t)b * LK * EB;
        for (int l = half; l < kli; l += 2)
            acc += sSc[l] * (kb[l * EB + ei] + pos_emb[l * EB + ei]);
        sRed[t] = acc;
        __syncthreads();
        if (t < 128)
            out[(size_t)b * EB + t] = (sRed[t] + sRed[t + 128]) * inv;
    }
}

extern "C" void kernel_launch(void* const* d_in, const int* in_sizes, int n_in,
                              void* d_out, int out_size) {
    const float* query       = (const float*)d_in[0];
    const float* keys        = (const float*)d_in[1];
    const void*  keys_length = d_in[2];
    const float* pos_emb     = (const float*)d_in[3];
    const float* W1          = (const float*)d_in[4];
    const float* b1          = (const float*)d_in[5];
    const float* W2          = (const float*)d_in[6];
    const float* b2          = (const float*)d_in[7];
    const float* W3          = (const float*)d_in[8];
    const float* b3          = (const float*)d_in[9];
    float* out = (float*)d_out;

    const int B = in_sizes[2];  // 4096

    static int attr_done = 0;
    if (!attr_done) {
        cudaFuncSetAttribute(prep_kernel, cudaFuncAttributeMaxDynamicSharedMemorySize, 16512 * 4);
        cudaFuncSetAttribute(din_kernel,  cudaFuncAttributeMaxDynamicSharedMemorySize, SMEM_BYTES);
        attr_done = 1;
    }

    prep_kernel<<<129, 256, 16512 * 4>>>(W1, b1, query, (const unsigned int*)keys_length, B);
    din_kernel<<<4096, 256, SMEM_BYTES>>>(query, keys, keys_length, pos_emb,
                                          W1, b2, W2, W3, b3, out);
}

// round 4
// speedup vs baseline: 1.7544x; 1.7544x over previous
#include <cuda_runtime.h>
#include <cuda_bf16.h>
#include <cstdint>

// DIN sequence encoder, B=4096, L=200, E=A=128.
// Factorization: att_in@W1 = q@(W1a+W1c) + keys_p@[(W1b-W1c) + diag(q)*W1d]
// One CTA per batch row, 512 threads, 4x8 register tiles, fma.rn.f32x2.

#define EB 128
#define AB 128
#define LK 200
#define NB 4096
#define STRK 132                 // Kt/H1 row stride (floats), 16B-aligned

__device__ float g_W1k[EB * AB];     // W1b - W1c
__device__ float g_U[NB * AB];       // per-batch u = q @ (W1a+W1c) + b1
__device__ int   g_len64;            // 1 if keys_length is int64

// ---------------- prep kernel: grid 129 x 256 ----------------
__global__ void prep_kernel(const float* __restrict__ W1,
                            const float* __restrict__ b1,
                            const float* __restrict__ query,
                            const unsigned int* __restrict__ kl_words, int B) {
    extern __shared__ float sp[];           // 16384 (W1q) + 128 (q)
    const int t = threadIdx.x;
    const int blk = blockIdx.x;

    if (blk < 64) {
        int i = blk * 256 + t;
        g_W1k[i] = W1[EB * AB + i] - W1[2 * EB * AB + i];
        return;
    }
    if (blk == 64) {
        int local = 0;
        for (int i = t; i < B / 2; i += 256)
            if (kl_words[2 * i + 1] != 0u) local = 1;
        int any = __syncthreads_or(local);
        if (t == 0) g_len64 = any ? 0 : 1;
        return;
    }

    float* sW = sp;
    float* sq = sp + 16384;
    for (int i = t; i < EB * AB; i += 256)
        sW[i] = W1[i] + W1[2 * EB * AB + i];
    __syncthreads();

    int bid2 = blk - 65;       // 0..63
    for (int bb2 = 0; bb2 < 64; bb2++) {
        int bb = bid2 * 64 + bb2;
        if (t < 128) sq[t] = query[(size_t)bb * EB + t];
        __syncthreads();
        if (t < 128) {
            float acc = b1[t];
            #pragma unroll 8
            for (int e = 0; e < EB; e++) acc += sq[e] * sW[e * AB + t];
            g_U[(size_t)bb * AB + t] = acc;
        }
        __syncthreads();
    }
}

// ---------------- f32x2 helpers ----------------
__device__ __forceinline__ unsigned long long packdup(float x) {
    unsigned long long r;
    asm("mov.b64 %0, {%1,%1};" : "=l"(r) : "f"(x));
    return r;
}
__device__ __forceinline__ void unpack2(unsigned long long v, float& lo, float& hi) {
    asm("mov.b64 {%0,%1}, %2;" : "=f"(lo), "=f"(hi) : "l"(v));
}
__device__ __forceinline__ void fma2(unsigned long long& d, unsigned long long a, unsigned long long b) {
    asm("fma.rn.f32x2 %0, %1, %2, %0;" : "+l"(d) : "l"(a), "l"(b));
}

// ---------------- SMEM layout (floats) ----------------
#define OFF_WB   0                        // 16384
#define OFF_W2   16384                    // 16384
#define OFF_KH   32768                    // 128*132 = 16896 (Kt then H1, reused)
#define OFF_Q    49664                    // 128
#define OFF_U    49792                    // 128
#define OFF_B2   49920                    // 128
#define OFF_W3   50048                    // 128
#define OFF_SC   50176                    // 256
#define OFF_RED  50432                    // 512
#define SMEM_FLOATS 50944
#define SMEM_BYTES  (SMEM_FLOATS * 4)

__global__ void __launch_bounds__(512, 1) din_kernel(
    const float* __restrict__ query,
    const float* __restrict__ keys,
    const void*  __restrict__ keys_length,
    const float* __restrict__ pos_emb,
    const float* __restrict__ W1,
    const float* __restrict__ b2,
    const float* __restrict__ W2,
    const float* __restrict__ W3,
    const float* __restrict__ b3,
    float* __restrict__ out)
{
    extern __shared__ float sm[];
    float* sWb  = sm + OFF_WB;
    float* sW2  = sm + OFF_W2;
    float* sKH  = sm + OFF_KH;
    float* sQ   = sm + OFF_Q;
    float* sU   = sm + OFF_U;
    float* sB2  = sm + OFF_B2;
    float* sW3  = sm + OFF_W3;
    float* sSc  = sm + OFF_SC;
    float* sRed = sm + OFF_RED;

    const int b = blockIdx.x;
    const int t = threadIdx.x;

    // ---- setup ----
    if (t < 128) {
        sQ[t]  = query[(size_t)b * EB + t];
        sU[t]  = g_U[(size_t)b * AB + t];
        sB2[t] = b2[t];
        sW3[t] = W3[t];
    }
    __syncthreads();

    const float* W1d = W1 + 3 * EB * AB;
    #pragma unroll 4
    for (int i = t; i < EB * AB; i += 512) {
        int e = i >> 7;
        sWb[i] = g_W1k[i] + sQ[e] * W1d[i];
        sW2[i] = W2[i];
    }
    const float b3v = b3[0];
    __syncthreads();

    // thread tiling: 4 l-rows x 8 a-cols per thread, 512 threads cover 128x128
    const int lt = t >> 4;            // 0..31 -> rows lb..lb+3
    const int at = t & 15;            // 0..15
    const int lb = lt * 4;
    const int c0 = 4 * at;
    const int c1 = 64 + 4 * at;

    for (int tile = 0; tile < 2; tile++) {
        const int l0 = tile * 128;

        // ---- stage keys_p tile transposed: sKH[e*STRK + l] ----
        #pragma unroll 4
        for (int idx = t; idx < 128 * EB; idx += 512) {
            int l = idx >> 7, e = idx & 127;
            int gl = l0 + l;
            float v = 0.0f;
            if (gl < LK)
                v = keys[((size_t)b * LK + gl) * EB + e] + pos_emb[gl * EB + e];
            sKH[e * STRK + l] = v;
        }
        __syncthreads();

        // ---- GEMM1: z1[l,a] = keys_p @ Wb ----
        unsigned long long acc[4][4];
        #pragma unroll
        for (int j = 0; j < 4; j++)
            #pragma unroll
            for (int k = 0; k < 4; k++) acc[j][k] = 0ULL;

        #pragma unroll 4
        for (int e = 0; e < EB; e++) {
            float4 a0 = *(const float4*)(sKH + e * STRK + lb);
            ulonglong2 bv0 = *(const ulonglong2*)(sWb + e * AB + c0);
            ulonglong2 bv1 = *(const ulonglong2*)(sWb + e * AB + c1);
            unsigned long long d0 = packdup(a0.x), d1 = packdup(a0.y);
            unsigned long long d2 = packdup(a0.z), d3 = packdup(a0.w);
            fma2(acc[0][0], d0, bv0.x); fma2(acc[0][1], d0, bv0.y);
            fma2(acc[0][2], d0, bv1.x); fma2(acc[0][3], d0, bv1.y);
            fma2(acc[1][0], d1, bv0.x); fma2(acc[1][1], d1, bv0.y);
            fma2(acc[1][2], d1, bv1.x); fma2(acc[1][3], d1, bv1.y);
            fma2(acc[2][0], d2, bv0.x); fma2(acc[2][1], d2, bv0.y);
            fma2(acc[2][2], d2, bv1.x); fma2(acc[2][3], d2, bv1.y);
            fma2(acc[3][0], d3, bv0.x); fma2(acc[3][1], d3, bv0.y);
            fma2(acc[3][2], d3, bv1.x); fma2(acc[3][3], d3, bv1.y);
        }
        __syncthreads();   // all Kt reads done -> safe to overwrite with H1

        // ---- epilogue 1: H1[col][l] = relu(z1 + u[col]) into sKH ----
        #pragma unroll
        for (int kk = 0; kk < 4; kk++) {
            int colL = (kk < 2) ? (c0 + 2 * kk) : (c1 + 2 * (kk - 2));
            int colH = colL + 1;
            float uL = sU[colL], uH = sU[colH];
            float loA[4], hiA[4];
            #pragma unroll
            for (int j = 0; j < 4; j++) {
                float lo, hi;
                unpack2(acc[j][kk], lo, hi);
                loA[j] = fmaxf(lo + uL, 0.0f);
                hiA[j] = fmaxf(hi + uH, 0.0f);
            }
            *(float4*)(sKH + colL * STRK + lb) = make_float4(loA[0], loA[1], loA[2], loA[3]);
            *(float4*)(sKH + colH * STRK + lb) = make_float4(hiA[0], hiA[1], hiA[2], hiA[3]);
        }
        __syncthreads();

        // ---- GEMM2: z2[l,a] = H1 @ W2 ----
        #pragma unroll
        for (int j = 0; j < 4; j++)
            #pragma unroll
            for (int k = 0; k < 4; k++) acc[j][k] = 0ULL;

        #pragma unroll 4
        for (int e = 0; e < AB; e++) {
            float4 a0 = *(const float4*)(sKH + e * STRK + lb);
            ulonglong2 bv0 = *(const ulonglong2*)(sW2 + e * AB + c0);
            ulonglong2 bv1 = *(const ulonglong2*)(sW2 + e * AB + c1);
            unsigned long long d0 = packdup(a0.x), d1 = packdup(a0.y);
            unsigned long long d2 = packdup(a0.z), d3 = packdup(a0.w);
            fma2(acc[0][0], d0, bv0.x); fma2(acc[0][1], d0, bv0.y);
            fma2(acc[0][2], d0, bv1.x); fma2(acc[0][3], d0, bv1.y);
            fma2(acc[1][0], d1, bv0.x); fma2(acc[1][1], d1, bv0.y);
            fma2(acc[1][2], d1, bv1.x); fma2(acc[1][3], d1, bv1.y);
            fma2(acc[2][0], d2, bv0.x); fma2(acc[2][1], d2, bv0.y);
            fma2(acc[2][2], d2, bv1.x); fma2(acc[2][3], d2, bv1.y);
            fma2(acc[3][0], d3, bv0.x); fma2(acc[3][1], d3, bv0.y);
            fma2(acc[3][2], d3, bv1.x); fma2(acc[3][3], d3, bv1.y);
        }

        // ---- epilogue 2: scores = sum_col relu(z2 + b2)*w3 ----
        {
            float sc[4] = {0, 0, 0, 0};
            #pragma unroll
            for (int kk = 0; kk < 4; kk++) {
                int colL = (kk < 2) ? (c0 + 2 * kk) : (c1 + 2 * (kk - 2));
                int colH = colL + 1;
                float bL = sB2[colL], bH = sB2[colH];
                float wL = sW3[colL], wH = sW3[colH];
                #pragma unroll
                for (int j = 0; j < 4; j++) {
                    float lo, hi;
                    unpack2(acc[j][kk], lo, hi);
                    sc[j] += fmaxf(lo + bL, 0.0f) * wL + fmaxf(hi + bH, 0.0f) * wH;
                }
            }
            #pragma unroll
            for (int off = 8; off > 0; off >>= 1)
                #pragma unroll
                for (int j = 0; j < 4; j++)
                    sc[j] += __shfl_down_sync(0xffffffffu, sc[j], off, 16);
            if (at == 0) {
                #pragma unroll
                for (int j = 0; j < 4; j++)
                    sSc[l0 + lb + j] = sc[j] + b3v;
            }
        }
        __syncthreads();
    }

    // ---- softmax over valid l ----
    int kli;
    if (g_len64) kli = (int)((const long long*)keys_length)[b];
    else         kli = ((const int*)keys_length)[b];
    kli = min(max(kli, 0), LK);

    const int wid = t >> 5, lane = t & 31;
    float s = (t < kli) ? sSc[t] : -3.0e38f;
    float mw = s;
    #pragma unroll
    for (int off = 16; off > 0; off >>= 1)
        mw = fmaxf(mw, __shfl_down_sync(0xffffffffu, mw, off));
    if (lane == 0) sRed[wid] = mw;
    __syncthreads();
    float m = sRed[0];
    #pragma unroll
    for (int w = 1; w < 16; w++) m = fmaxf(m, sRed[w]);

    float wgt = (t < kli) ? expf(s - m) : 0.0f;
    if (t < 256) sSc[t] = wgt;
    float sw = wgt;
    #pragma unroll
    for (int off = 16; off > 0; off >>= 1)
        sw += __shfl_down_sync(0xffffffffu, sw, off);
    if (lane == 0) sRed[16 + wid] = sw;
    __syncthreads();
    float tot = 0.0f;
    #pragma unroll
    for (int w = 0; w < 16; w++) tot += sRed[16 + w];
    const float inv = 1.0f / tot;
    __syncthreads();

    // ---- weighted sum of keys_p ----
    {
        int ei = t & 127, quarter = t >> 7;   // 0..3
        float acc = 0.0f;
        const float* kb = keys + (size_t)b * LK * EB;
        for (int l = quarter; l < kli; l += 4)
            acc += sSc[l] * (kb[l * EB + ei] + pos_emb[l * EB + ei]);
        sRed[t] = acc;
        __syncthreads();
        if (t < 128)
            out[(size_t)b * EB + t] =
                (sRed[t] + sRed[t + 128] + sRed[t + 256] + sRed[t + 384]) * inv;
    }
}

extern "C" void kernel_launch(void* const* d_in, const int* in_sizes, int n_in,
                              void* d_out, int out_size) {
    const float* query       = (const float*)d_in[0];
    const float* keys        = (const float*)d_in[1];
    const void*  keys_length = d_in[2];
    const float* pos_emb     = (const float*)d_in[3];
    const float* W1          = (const float*)d_in[4];
    const float* b1          = (const float*)d_in[5];
    const float* W2          = (const float*)d_in[6];
    const float* b2          = (const float*)d_in[7];
    const float* W3          = (const float*)d_in[8];
    const float* b3          = (const float*)d_in[9];
    float* out = (float*)d_out;

    const int B = in_sizes[2];  // 4096

    static int attr_done = 0;
    if (!attr_done) {
        cudaFuncSetAttribute(prep_kernel, cudaFuncAttributeMaxDynamicSharedMemorySize, 16512 * 4);
        cudaFuncSetAttribute(din_kernel,  cudaFuncAttributeMaxDynamicSharedMemorySize, SMEM_BYTES);
        attr_done = 1;
    }

    prep_kernel<<<129, 256, 16512 * 4>>>(W1, b1, query, (const unsigned int*)keys_length, B);
    din_kernel<<<4096, 512, SMEM_BYTES>>>(query, keys, keys_length, pos_emb,
                                          W1, b2, W2, W3, b3, out);
}

// round 6
// speedup vs baseline: 3.4402x; 1.9609x over previous
#include <cuda_runtime.h>
#include <cuda_bf16.h>
#include <cstdint>

// DIN sequence encoder, B=4096, L=200, E=A=128.
// Factorization: att_in@W1 = q@(W1a+W1c) + keys_p@[(W1b-W1c) + diag(q)*W1d]
// One CTA per batch row, 512 threads. Both 128x128x128 GEMMs on legacy
// tensor cores (mma.sync m16n8k16 bf16, fp32 accum) with a 3-term bf16
// split (AhBh + AhBl + AlBh) for ~fp32 accuracy. compute_103-safe PTX only.

#define EB 128
#define AB 128
#define LK 200
#define NB 4096
#define LDAE 136                 // padded row stride in bf16 elements
#define LDAB (LDAE * 2)          // 272 bytes; 8-row ldmatrix is bank-conflict-free

__device__ float g_W1kT[EB * AB];                    // [n][e] = (W1b - W1c)^T
__device__ float g_W1dT[EB * AB];                    // [n][e] = W1d^T
__device__ __align__(16) uint32_t g_W2Thi[128 * 68]; // W2^T hi, padded [n][k] bf16 pairs
__device__ __align__(16) uint32_t g_W2Tlo[128 * 68]; // W2^T lo
__device__ float g_U[NB * AB];                       // u = q @ (W1a+W1c) + b1
__device__ int   g_len64;

__device__ __forceinline__ uint32_t packsplit(float x0, float x1, uint32_t& lop) {
    __nv_bfloat16 h0 = __float2bfloat16(x0);
    __nv_bfloat16 h1 = __float2bfloat16(x1);
    __nv_bfloat16 l0 = __float2bfloat16(x0 - __bfloat162float(h0));
    __nv_bfloat16 l1 = __float2bfloat16(x1 - __bfloat162float(h1));
    lop = ((uint32_t)__bfloat16_as_ushort(l1) << 16) | (uint32_t)__bfloat16_as_ushort(l0);
    return ((uint32_t)__bfloat16_as_ushort(h1) << 16) | (uint32_t)__bfloat16_as_ushort(h0);
}

// ---------------- prep kernel: grid 161 x 256 ----------------
__global__ void prep_kernel(const float* __restrict__ W1,
                            const float* __restrict__ b1,
                            const float* __restrict__ W2,
                            const float* __restrict__ query,
                            const unsigned int* __restrict__ kl_words, int B) {
    extern __shared__ float sp[];
    const int t = threadIdx.x;
    const int blk = blockIdx.x;

    if (blk < 64) {                       // W1 transposes (fp32)
        int i = blk * 256 + t;
        int e = i >> 7, n = i & 127;
        g_W1kT[n * EB + e] = W1[EB * AB + e * AB + n] - W1[2 * EB * AB + e * AB + n];
        g_W1dT[n * EB + e] = W1[3 * EB * AB + e * AB + n];
        return;
    }
    if (blk < 96) {                       // W2^T split into padded bf16 hi/lo
        int i = (blk - 64) * 256 + t;     // 0..8191
        int e2 = (i >> 7) * 2, n = i & 127;
        float x0 = W2[e2 * AB + n];
        float x1 = W2[(e2 + 1) * AB + n];
        uint32_t lop, hip = packsplit(x0, x1, lop);
        uint32_t wi = n * 68 + (e2 >> 1);
        g_W2Thi[wi] = hip;
        g_W2Tlo[wi] = lop;
        return;
    }
    if (blk == 96) {                      // keys_length dtype sniffer
        int local = 0;
        for (int i = t; i < B / 2; i += 256)
            if (kl_words[2 * i + 1] != 0u) local = 1;
        int any = __syncthreads_or(local);
        if (t == 0) g_len64 = any ? 0 : 1;
        return;
    }

    // g_U blocks (97..160)
    float* sW = sp;            // 16384: W1a + W1c
    float* sq = sp + 16384;    // 128
    for (int i = t; i < EB * AB; i += 256)
        sW[i] = W1[i] + W1[2 * EB * AB + i];
    __syncthreads();
    int bid2 = blk - 97;
    for (int bb2 = 0; bb2 < 64; bb2++) {
        int bb = bid2 * 64 + bb2;
        if (t < 128) sq[t] = query[(size_t)bb * EB + t];
        __syncthreads();
        if (t < 128) {
            float acc = b1[t];
            #pragma unroll 8
            for (int e = 0; e < EB; e++) acc += sq[e] * sW[e * AB + t];
            g_U[(size_t)bb * AB + t] = acc;
        }
        __syncthreads();
    }
}

// ---------------- MMA helpers (compute_103-safe) ----------------
__device__ __forceinline__ uint32_t smem_u32(const void* p) {
    uint32_t a;
    asm("{ .reg .u64 tmp; cvta.to.shared.u64 tmp, %1; cvt.u32.u64 %0, tmp; }"
        : "=r"(a) : "l"(p));
    return a;
}
__device__ __forceinline__ void ldsm_x4(uint32_t* r, uint32_t addr) {
    asm volatile("ldmatrix.sync.aligned.m8n8.x4.shared.b16 {%0,%1,%2,%3}, [%4];"
                 : "=r"(r[0]), "=r"(r[1]), "=r"(r[2]), "=r"(r[3]) : "r"(addr));
}
__device__ __forceinline__ void mma_bf16(float* d, const uint32_t* a, const uint32_t* b) {
    asm volatile("mma.sync.aligned.m16n8k16.row.col.f32.bf16.bf16.f32 "
                 "{%0,%1,%2,%3},{%4,%5,%6,%7},{%8,%9},{%0,%1,%2,%3};"
                 : "+f"(d[0]), "+f"(d[1]), "+f"(d[2]), "+f"(d[3])
                 : "r"(a[0]), "r"(a[1]), "r"(a[2]), "r"(a[3]), "r"(b[0]), "r"(b[1]));
}

// 3-term split GEMM: warp computes 32x32 block. A:[128 rows][LDAE], B:[128 n][LDAE].
__device__ __forceinline__ void warp_gemm3(uint32_t aHi, uint32_t aLo,
                                           uint32_t bHi, uint32_t bLo,
                                           uint32_t aoffb, uint32_t boffb,
                                           float acc[2][4][4]) {
    #pragma unroll
    for (int k = 0; k < 8; k++) {
        uint32_t ao = aoffb + k * 32;   // k16 step = 32 bytes
        uint32_t bo = boffb + k * 32;
        uint32_t ah[2][4], al[2][4], bh[8], bl[8];
        ldsm_x4(ah[0], aHi + ao); ldsm_x4(ah[1], aHi + ao + 16 * LDAB);
        ldsm_x4(al[0], aLo + ao); ldsm_x4(al[1], aLo + ao + 16 * LDAB);
        ldsm_x4(bh,     bHi + bo); ldsm_x4(bh + 4, bHi + bo + 16 * LDAB);
        ldsm_x4(bl,     bLo + bo); ldsm_x4(bl + 4, bLo + bo + 16 * LDAB);
        #pragma unroll
        for (int mt = 0; mt < 2; mt++)
            #pragma unroll
            for (int nt = 0; nt < 4; nt++)
                mma_bf16(acc[mt][nt], ah[mt], bh + nt * 2);
        #pragma unroll
        for (int mt = 0; mt < 2; mt++)
            #pragma unroll
            for (int nt = 0; nt < 4; nt++)
                mma_bf16(acc[mt][nt], ah[mt], bl + nt * 2);
        #pragma unroll
        for (int mt = 0; mt < 2; mt++)
            #pragma unroll
            for (int nt = 0; nt < 4; nt++)
                mma_bf16(acc[mt][nt], al[mt], bh + nt * 2);
    }
}

// ---------------- SMEM layout (bytes) ----------------
#define TILEB (128 * LDAB)       // 34816
#define OFF_AHI  0
#define OFF_ALO  (OFF_AHI  + TILEB)
#define OFF_B1HI (OFF_ALO  + TILEB)
#define OFF_B1LO (OFF_B1HI + TILEB)
#define OFF_B2HI (OFF_B1LO + TILEB)
#define OFF_B2LO (OFF_B2HI + TILEB)   // ends 208896
#define OFF_Q    208896
#define OFF_U    209408
#define OFF_BB2  209920
#define OFF_W3   210432
#define OFF_SC   210944               // 256 floats
#define OFF_RED  211968               // 512 floats
#define SMEM_BYTES 214016

__global__ void __launch_bounds__(512, 1) din_kernel(
    const float* __restrict__ query,
    const float* __restrict__ keys,
    const void*  __restrict__ keys_length,
    const float* __restrict__ pos_emb,
    const float* __restrict__ b2,
    const float* __restrict__ W3,
    const float* __restrict__ b3,
    float* __restrict__ out)
{
    extern __shared__ char smc[];
    float* sQ   = (float*)(smc + OFF_Q);
    float* sU   = (float*)(smc + OFF_U);
    float* sBB  = (float*)(smc + OFF_BB2);
    float* sW3  = (float*)(smc + OFF_W3);
    float* sSc  = (float*)(smc + OFF_SC);
    float* sRed = (float*)(smc + OFF_RED);

    const int b = blockIdx.x;
    const int t = threadIdx.x;
    const int w = t >> 5, lane = t & 31;

    if (t < 128) {
        sQ[t]  = query[(size_t)b * EB + t];
        sU[t]  = g_U[(size_t)b * AB + t];
        sBB[t] = b2[t];
        sW3[t] = W3[t];
    }
    __syncthreads();
    const float b3v = b3[0];

    // ---- stage B1 = WbT split (depends on q) ----
    {
        uint32_t* hi = (uint32_t*)(smc + OFF_B1HI);
        uint32_t* lo = (uint32_t*)(smc + OFF_B1LO);
        #pragma unroll 4
        for (int i = t; i < 8192; i += 512) {
            int n = i >> 6, e2 = (i & 63) * 2;
            float x0 = g_W1kT[n * EB + e2]     + sQ[e2]     * g_W1dT[n * EB + e2];
            float x1 = g_W1kT[n * EB + e2 + 1] + sQ[e2 + 1] * g_W1dT[n * EB + e2 + 1];
            uint32_t lop, hip = packsplit(x0, x1, lop);
            uint32_t wi = n * 68 + (i & 63);
            hi[wi] = hip;
            lo[wi] = lop;
        }
    }
    // ---- copy B2 = W2T split (precomputed, identical padded layout) ----
    {
        const uint4* shi = (const uint4*)g_W2Thi;
        const uint4* slo = (const uint4*)g_W2Tlo;
        uint4* dhi = (uint4*)(smc + OFF_B2HI);
        uint4* dlo = (uint4*)(smc + OFF_B2LO);
        for (int i = t; i < 2176; i += 512) { dhi[i] = shi[i]; dlo[i] = slo[i]; }
    }

    const uint32_t aHi  = smem_u32(smc + OFF_AHI);
    const uint32_t aLo  = smem_u32(smc + OFF_ALO);
    const uint32_t b1Hi = smem_u32(smc + OFF_B1HI);
    const uint32_t b1Lo = smem_u32(smc + OFF_B1LO);
    const uint32_t b2Hi = smem_u32(smc + OFF_B2HI);
    const uint32_t b2Lo = smem_u32(smc + OFF_B2LO);

    const int m0 = (w >> 2) * 32;      // warp's row block
    const int n0 = (w & 3) * 32;       // warp's col block
    // ldmatrix per-lane source offsets
    const uint32_t arow = m0 + (((lane >> 3) & 1) << 3) + (lane & 7);
    const uint32_t acol = ((lane >> 4) << 3);
    const uint32_t aoffb = arow * LDAB + acol * 2;
    const uint32_t brow = n0 + ((lane >> 4) << 3) + (lane & 7);
    const uint32_t bcol = (((lane >> 3) & 1) << 3);
    const uint32_t boffb = brow * LDAB + bcol * 2;

    for (int tile = 0; tile < 2; tile++) {
        const int l0 = tile * 128;

        // ---- stage A = keys_p tile, hi/lo split ----
        {
            uint32_t* hi = (uint32_t*)(smc + OFF_AHI);
            uint32_t* lo = (uint32_t*)(smc + OFF_ALO);
            #pragma unroll 4
            for (int i = t; i < 8192; i += 512) {
                int l = i >> 6, e2 = (i & 63) * 2;
                int gl = l0 + l;
                float x0 = 0.0f, x1 = 0.0f;
                if (gl < LK) {
                    float2 kv = *(const float2*)(keys + ((size_t)b * LK + gl) * EB + e2);
                    float2 pv = *(const float2*)(pos_emb + (size_t)gl * EB + e2);
                    x0 = kv.x + pv.x; x1 = kv.y + pv.y;
                }
                uint32_t lop, hip = packsplit(x0, x1, lop);
                uint32_t wi = l * 68 + (i & 63);
                hi[wi] = hip;
                lo[wi] = lop;
            }
        }
        __syncthreads();

        // ---- layer 1 GEMM ----
        float acc[2][4][4];
        #pragma unroll
        for (int mt = 0; mt < 2; mt++)
            #pragma unroll
            for (int nt = 0; nt < 4; nt++)
                #pragma unroll
                for (int r = 0; r < 4; r++) acc[mt][nt][r] = 0.0f;
        warp_gemm3(aHi, aLo, b1Hi, b1Lo, aoffb, boffb, acc);
        __syncthreads();   // all A reads done -> safe to overwrite with H1

        // ---- epilogue 1: H1 = relu(z1 + u) -> A buffers ----
        {
            uint32_t* hi = (uint32_t*)(smc + OFF_AHI);
            uint32_t* lo = (uint32_t*)(smc + OFF_ALO);
            const int rrow = lane >> 2;
            const int ccol = (lane & 3) * 2;
            #pragma unroll
            for (int mt = 0; mt < 2; mt++) {
                #pragma unroll
                for (int nt = 0; nt < 4; nt++) {
                    int c = n0 + nt * 8 + ccol;
                    float u0 = sU[c], u1 = sU[c + 1];
                    int r0 = m0 + mt * 16 + rrow;
                    float h0 = fmaxf(acc[mt][nt][0] + u0, 0.0f);
                    float h1 = fmaxf(acc[mt][nt][1] + u1, 0.0f);
                    uint32_t lop, hip = packsplit(h0, h1, lop);
                    uint32_t wi = r0 * 68 + (c >> 1);
                    hi[wi] = hip; lo[wi] = lop;
                    h0 = fmaxf(acc[mt][nt][2] + u0, 0.0f);
                    h1 = fmaxf(acc[mt][nt][3] + u1, 0.0f);
                    hip = packsplit(h0, h1, lop);
                    wi = (r0 + 8) * 68 + (c >> 1);
                    hi[wi] = hip; lo[wi] = lop;
                }
            }
        }
        __syncthreads();

        // ---- layer 2 GEMM ----
        #pragma unroll
        for (int mt = 0; mt < 2; mt++)
            #pragma unroll
            for (int nt = 0; nt < 4; nt++)
                #pragma unroll
                for (int r = 0; r < 4; r++) acc[mt][nt][r] = 0.0f;
        warp_gemm3(aHi, aLo, b2Hi, b2Lo, aoffb, boffb, acc);

        // ---- epilogue 2: scores = sum_col relu(z2 + b2)*w3 ----
        {
            const int ccol = (lane & 3) * 2;
            float part[2][2] = {{0.f, 0.f}, {0.f, 0.f}};
            #pragma unroll
            for (int mt = 0; mt < 2; mt++) {
                #pragma unroll
                for (int nt = 0; nt < 4; nt++) {
                    int c = n0 + nt * 8 + ccol;
                    float bb0 = sBB[c], bb1 = sBB[c + 1];
                    float w30 = sW3[c], w31 = sW3[c + 1];
                    part[mt][0] += fmaxf(acc[mt][nt][0] + bb0, 0.0f) * w30
                                 + fmaxf(acc[mt][nt][1] + bb1, 0.0f) * w31;
                    part[mt][1] += fmaxf(acc[mt][nt][2] + bb0, 0.0f) * w30
                                 + fmaxf(acc[mt][nt][3] + bb1, 0.0f) * w31;
                }
            }
            #pragma unroll
            for (int mt = 0; mt < 2; mt++)
                #pragma unroll
                for (int rh = 0; rh < 2; rh++) {
                    part[mt][rh] += __shfl_xor_sync(0xffffffffu, part[mt][rh], 1);
                    part[mt][rh] += __shfl_xor_sync(0xffffffffu, part[mt][rh], 2);
                }
            if ((lane & 3) == 0) {
                int rbase = m0 + (lane >> 2);
                sRed[(rbase)      * 4 + (w & 3)] = part[0][0];
                sRed[(rbase + 8)  * 4 + (w & 3)] = part[0][1];
                sRed[(rbase + 16) * 4 + (w & 3)] = part[1][0];
                sRed[(rbase + 24) * 4 + (w & 3)] = part[1][1];
            }
        }
        __syncthreads();
        if (t < 128)
            sSc[l0 + t] = sRed[t * 4] + sRed[t * 4 + 1] + sRed[t * 4 + 2] + sRed[t * 4 + 3] + b3v;
        __syncthreads();
    }

    // ---- softmax over valid l ----
    int kli;
    if (g_len64) kli = (int)((const long long*)keys_length)[b];
    else         kli = ((const int*)keys_length)[b];
    kli = min(max(kli, 0), LK);

    float s = (t < kli) ? sSc[t] : -3.0e38f;
    float mw = s;
    #pragma unroll
    for (int off = 16; off > 0; off >>= 1)
        mw = fmaxf(mw, __shfl_down_sync(0xffffffffu, mw, off));
    if (lane == 0) sRed[w] = mw;
    __syncthreads();
    float m = sRed[0];
    #pragma unroll
    for (int ww = 1; ww < 16; ww++) m = fmaxf(m, sRed[ww]);

    float wgt = (t < kli) ? expf(s - m) : 0.0f;
    if (t < 256) sSc[t] = wgt;
    float sw = wgt;
    #pragma unroll
    for (int off = 16; off > 0; off >>= 1)
        sw += __shfl_down_sync(0xffffffffu, sw, off);
    if (lane == 0) sRed[16 + w] = sw;
    __syncthreads();
    float tot = 0.0f;
    #pragma unroll
    for (int ww = 0; ww < 16; ww++) tot += sRed[16 + ww];
    const float inv = 1.0f / tot;
    __syncthreads();

    // ---- weighted sum of keys_p ----
    {
        int ei = t & 127, quarter = t >> 7;
        float acc2 = 0.0f;
        const float* kb = keys + (size_t)b * LK * EB;
        for (int l = quarter; l < kli; l += 4)
            acc2 += sSc[l] * (kb[l * EB + ei] + pos_emb[l * EB + ei]);
        sRed[t] = acc2;
        __syncthreads();
        if (t < 128)
            out[(size_t)b * EB + t] =
                (sRed[t] + sRed[t + 128] + sRed[t + 256] + sRed[t + 384]) * inv;
    }
}

extern "C" void kernel_launch(void* const* d_in, const int* in_sizes, int n_in,
                              void* d_out, int out_size) {
    const float* query       = (const float*)d_in[0];
    const float* keys        = (const float*)d_in[1];
    const void*  keys_length = d_in[2];
    const float* pos_emb     = (const float*)d_in[3];
    const float* W1          = (const float*)d_in[4];
    const float* b1          = (const float*)d_in[5];
    const float* W2          = (const float*)d_in[6];
    const float* b2          = (const float*)d_in[7];
    const float* W3          = (const float*)d_in[8];
    const float* b3          = (const float*)d_in[9];
    float* out = (float*)d_out;

    const int B = in_sizes[2];  // 4096

    static int attr_done = 0;
    if (!attr_done) {
        cudaFuncSetAttribute(prep_kernel, cudaFuncAttributeMaxDynamicSharedMemorySize, 16512 * 4);
        cudaFuncSetAttribute(din_kernel,  cudaFuncAttributeMaxDynamicSharedMemorySize, SMEM_BYTES);
        attr_done = 1;
    }

    prep_kernel<<<161, 256, 16512 * 4>>>(W1, b1, W2, query,
                                         (const unsigned int*)keys_length, B);
    din_kernel<<<4096, 512, SMEM_BYTES>>>(query, keys, keys_length, pos_emb,
                                          b2, W3, b3, out);
}

// round 7
// speedup vs baseline: 3.9029x; 1.1345x over previous
#include <cuda_runtime.h>
#include <cuda_bf16.h>
#include <cstdint>

// DIN sequence encoder, B=4096, L=200, E=A=128.
// Factorization: att_in@W1 = q@(W1a+W1c) + keys_p@[(W1b-W1c) + diag(q)*W1d]
// 256 threads/CTA, 2 CTAs/SM. 64-row l-tiles. Both GEMMs on mma.sync bf16
// (3-term split). B1 (q-dependent) in smem via ldmatrix; B2 (W2) streamed
// from gmem in a precomputed per-thread fragment layout (LDG.128).

#define EB 128
#define AB 128
#define LK 200
#define NB 4096
#define LDAE 136
#define LDAB (LDAE * 2)          // 272 B row stride

__device__ float g_W1kT[EB * AB];                    // [n][e] = (W1b - W1c)^T
__device__ float g_W1dT[EB * AB];                    // [n][e] = W1d^T
__device__ __align__(16) uint32_t g_W2fh[8192];      // W2 hi fragments (per-thread images)
__device__ __align__(16) uint32_t g_W2fl[8192];      // W2 lo fragments
__device__ float g_U[NB * AB];                       // u = q @ (W1a+W1c) + b1
__device__ int   g_len64;

__device__ __forceinline__ uint32_t packsplit(float x0, float x1, uint32_t& lop) {
    __nv_bfloat16 h0 = __float2bfloat16(x0);
    __nv_bfloat16 h1 = __float2bfloat16(x1);
    __nv_bfloat16 l0 = __float2bfloat16(x0 - __bfloat162float(h0));
    __nv_bfloat16 l1 = __float2bfloat16(x1 - __bfloat162float(h1));
    lop = ((uint32_t)__bfloat16_as_ushort(l1) << 16) | (uint32_t)__bfloat16_as_ushort(l0);
    return ((uint32_t)__bfloat16_as_ushort(h1) << 16) | (uint32_t)__bfloat16_as_ushort(h0);
}

// ---------------- prep kernel: grid 161 x 256 ----------------
__global__ void prep_kernel(const float* __restrict__ W1,
                            const float* __restrict__ b1,
                            const float* __restrict__ W2,
                            const float* __restrict__ query,
                            const unsigned int* __restrict__ kl_words, int B) {
    extern __shared__ float sp[];
    const int t = threadIdx.x;
    const int blk = blockIdx.x;

    if (blk < 64) {                       // W1 transposes (fp32)
        int i = blk * 256 + t;
        int e = i >> 7, n = i & 127;
        g_W1kT[n * EB + e] = W1[EB * AB + e * AB + n] - W1[2 * EB * AB + e * AB + n];
        g_W1dT[n * EB + e] = W1[3 * EB * AB + e * AB + n];
        return;
    }
    if (blk < 96) {                       // W2 fragment images for mma B operand
        int i = (blk - 64) * 256 + t;     // 0..8191
        // i = ((s*8+ng)*32 + lane)*4 + j
        int j = i & 3, lane = (i >> 2) & 31, ng = (i >> 7) & 7, s = i >> 10;
        int n  = ng * 16 + ((j >> 1) << 3) + (lane >> 2);
        int k0 = s * 16 + (lane & 3) * 2 + ((j & 1) ? 8 : 0);
        float a = W2[k0 * AB + n];
        float bv = W2[(k0 + 1) * AB + n];
        uint32_t lop, hip = packsplit(a, bv, lop);
        g_W2fh[i] = hip;
        g_W2fl[i] = lop;
        return;
    }
    if (blk == 96) {                      // keys_length dtype sniffer
        int local = 0;
        for (int i = t; i < B / 2; i += 256)
            if (kl_words[2 * i + 1] != 0u) local = 1;
        int any = __syncthreads_or(local);
        if (t == 0) g_len64 = any ? 0 : 1;
        return;
    }

    // g_U blocks (97..160)
    float* sW = sp;            // 16384: W1a + W1c
    float* sq = sp + 16384;    // 128
    for (int i = t; i < EB * AB; i += 256)
        sW[i] = W1[i] + W1[2 * EB * AB + i];
    __syncthreads();
    int bid2 = blk - 97;
    for (int bb2 = 0; bb2 < 64; bb2++) {
        int bb = bid2 * 64 + bb2;
        if (t < 128) sq[t] = query[(size_t)bb * EB + t];
        __syncthreads();
        if (t < 128) {
            float acc = b1[t];
            #pragma unroll 8
            for (int e = 0; e < EB; e++) acc += sq[e] * sW[e * AB + t];
            g_U[(size_t)bb * AB + t] = acc;
        }
        __syncthreads();
    }
}

// ---------------- MMA helpers ----------------
__device__ __forceinline__ uint32_t smem_u32(const void* p) {
    uint32_t a;
    asm("{ .reg .u64 tmp; cvta.to.shared.u64 tmp, %1; cvt.u32.u64 %0, tmp; }"
        : "=r"(a) : "l"(p));
    return a;
}
__device__ __forceinline__ void ldsm_x4(uint32_t* r, uint32_t addr) {
    asm volatile("ldmatrix.sync.aligned.m8n8.x4.shared.b16 {%0,%1,%2,%3}, [%4];"
                 : "=r"(r[0]), "=r"(r[1]), "=r"(r[2]), "=r"(r[3]) : "r"(addr));
}
__device__ __forceinline__ void mma_bf16(float* d, const uint32_t* a,
                                         uint32_t b0, uint32_t b1) {
    asm volatile("mma.sync.aligned.m16n8k16.row.col.f32.bf16.bf16.f32 "
                 "{%0,%1,%2,%3},{%4,%5,%6,%7},{%8,%9},{%0,%1,%2,%3};"
                 : "+f"(d[0]), "+f"(d[1]), "+f"(d[2]), "+f"(d[3])
                 : "r"(a[0]), "r"(a[1]), "r"(a[2]), "r"(a[3]), "r"(b0), "r"(b1));
}

// ---------------- SMEM layout (bytes) ----------------
#define OFF_AHI  0                        // 64*272 = 17408
#define OFF_ALO  17408
#define OFF_B1HI 34816                    // 128*272 = 34816
#define OFF_B1LO 69632
#define OFF_Q    104448
#define OFF_U    104960
#define OFF_BB2  105472
#define OFF_W3   105984
#define OFF_SC   106496                   // 256 floats
#define OFF_RED  107520                   // 512 floats
#define SMEM_BYTES 109568

__global__ void __launch_bounds__(256, 2) din_kernel(
    const float* __restrict__ query,
    const float* __restrict__ keys,
    const void*  __restrict__ keys_length,
    const float* __restrict__ pos_emb,
    const float* __restrict__ b2,
    const float* __restrict__ W3,
    const float* __restrict__ b3,
    float* __restrict__ out)
{
    extern __shared__ char smc[];
    float* sQ   = (float*)(smc + OFF_Q);
    float* sU   = (float*)(smc + OFF_U);
    float* sBB  = (float*)(smc + OFF_BB2);
    float* sW3  = (float*)(smc + OFF_W3);
    float* sSc  = (float*)(smc + OFF_SC);
    float* sRed = (float*)(smc + OFF_RED);

    const int b = blockIdx.x;
    const int t = threadIdx.x;
    const int w = t >> 5, lane = t & 31;

    if (t < 128) {
        sQ[t]  = query[(size_t)b * EB + t];
        sU[t]  = g_U[(size_t)b * AB + t];
        sBB[t] = b2[t];
        sW3[t] = W3[t];
    }
    __syncthreads();
    const float b3v = b3[0];

    // ---- stage B1 = WbT hi/lo (q-dependent) ----
    {
        uint32_t* hi = (uint32_t*)(smc + OFF_B1HI);
        uint32_t* lo = (uint32_t*)(smc + OFF_B1LO);
        #pragma unroll 4
        for (int i = t; i < 8192; i += 256) {
            int n = i >> 6, e2 = (i & 63) * 2;
            float x0 = g_W1kT[n * EB + e2]     + sQ[e2]     * g_W1dT[n * EB + e2];
            float x1 = g_W1kT[n * EB + e2 + 1] + sQ[e2 + 1] * g_W1dT[n * EB + e2 + 1];
            uint32_t lop, hip = packsplit(x0, x1, lop);
            uint32_t wi = n * 68 + (i & 63);
            hi[wi] = hip;
            lo[wi] = lop;
        }
    }

    const uint32_t aHi  = smem_u32(smc + OFF_AHI);
    const uint32_t aLo  = smem_u32(smc + OFF_ALO);
    const uint32_t b1Hi = smem_u32(smc + OFF_B1HI);
    const uint32_t b1Lo = smem_u32(smc + OFF_B1LO);

    const int ng = w;                         // 8 warps = 8 n-groups of 16 cols
    // shared lane pattern for ldmatrix (A frags and B1 frags)
    const uint32_t lrow = (((lane >> 3) & 1) << 3) + (lane & 7);
    const uint32_t lcolb = (lane >> 4) << 4;
    const uint32_t aFragOff  = lrow * LDAB + lcolb;
    const uint32_t b1FragOff = (ng * 16 + lrow) * LDAB + lcolb;

    const uint4* W2fh4 = (const uint4*)g_W2fh;
    const uint4* W2fl4 = (const uint4*)g_W2fl;

    for (int tile = 0; tile < 4; tile++) {
        const int l0 = tile * 64;

        // ---- stage A = keys_p tile (64 rows), hi/lo split ----
        {
            uint32_t* hi = (uint32_t*)(smc + OFF_AHI);
            uint32_t* lo = (uint32_t*)(smc + OFF_ALO);
            #pragma unroll 4
            for (int i = t; i < 4096; i += 256) {
                int l = i >> 6, e2 = (i & 63) * 2;
                int gl = l0 + l;
                float x0 = 0.0f, x1 = 0.0f;
                if (gl < LK) {
                    float2 kv = *(const float2*)(keys + ((size_t)b * LK + gl) * EB + e2);
                    float2 pv = *(const float2*)(pos_emb + (size_t)gl * EB + e2);
                    x0 = kv.x + pv.x; x1 = kv.y + pv.y;
                }
                uint32_t lop, hip = packsplit(x0, x1, lop);
                uint32_t wi = l * 68 + (i & 63);
                hi[wi] = hip;
                lo[wi] = lop;
            }
        }
        __syncthreads();

        float acc[4][2][4];
        // ---- layer 1 GEMM: 64x16 block per warp, B1 via ldmatrix ----
        #pragma unroll
        for (int mt = 0; mt < 4; mt++)
            #pragma unroll
            for (int nt = 0; nt < 2; nt++)
                #pragma unroll
                for (int r = 0; r < 4; r++) acc[mt][nt][r] = 0.0f;

        #pragma unroll
        for (int k = 0; k < 8; k++) {
            uint32_t ah[4][4], al[4][4], bh[4], bl[4];
            #pragma unroll
            for (int mt = 0; mt < 4; mt++) {
                ldsm_x4(ah[mt], aHi + aFragOff + mt * (16 * LDAB) + k * 32);
                ldsm_x4(al[mt], aLo + aFragOff + mt * (16 * LDAB) + k * 32);
            }
            ldsm_x4(bh, b1Hi + b1FragOff + k * 32);
            ldsm_x4(bl, b1Lo + b1FragOff + k * 32);
            // regs: nt0 pair = (r0, r2); nt1 pair = (r1, r3)
            #pragma unroll
            for (int mt = 0; mt < 4; mt++) {
                mma_bf16(acc[mt][0], ah[mt], bh[0], bh[2]);
                mma_bf16(acc[mt][1], ah[mt], bh[1], bh[3]);
            }
            #pragma unroll
            for (int mt = 0; mt < 4; mt++) {
                mma_bf16(acc[mt][0], ah[mt], bl[0], bl[2]);
                mma_bf16(acc[mt][1], ah[mt], bl[1], bl[3]);
            }
            #pragma unroll
            for (int mt = 0; mt < 4; mt++) {
                mma_bf16(acc[mt][0], al[mt], bh[0], bh[2]);
                mma_bf16(acc[mt][1], al[mt], bh[1], bh[3]);
            }
        }
        __syncthreads();   // A reads done -> safe to overwrite with H1

        // ---- epilogue 1: H1 = relu(z1 + u) -> A buffers ----
        {
            uint32_t* hi = (uint32_t*)(smc + OFF_AHI);
            uint32_t* lo = (uint32_t*)(smc + OFF_ALO);
            const int rrow = lane >> 2;
            const int ccol = (lane & 3) * 2;
            #pragma unroll
            for (int mt = 0; mt < 4; mt++) {
                #pragma unroll
                for (int nt = 0; nt < 2; nt++) {
                    int c = ng * 16 + nt * 8 + ccol;
                    float u0 = sU[c], u1 = sU[c + 1];
                    int r0 = mt * 16 + rrow;
                    float h0 = fmaxf(acc[mt][nt][0] + u0, 0.0f);
                    float h1 = fmaxf(acc[mt][nt][1] + u1, 0.0f);
                    uint32_t lop, hip = packsplit(h0, h1, lop);
                    uint32_t wi = r0 * 68 + (c >> 1);
                    hi[wi] = hip; lo[wi] = lop;
                    h0 = fmaxf(acc[mt][nt][2] + u0, 0.0f);
                    h1 = fmaxf(acc[mt][nt][3] + u1, 0.0f);
                    hip = packsplit(h0, h1, lop);
                    wi = (r0 + 8) * 68 + (c >> 1);
                    hi[wi] = hip; lo[wi] = lop;
                }
            }
        }
        __syncthreads();

        // ---- layer 2 GEMM: B = W2 fragments streamed from gmem ----
        #pragma unroll
        for (int mt = 0; mt < 4; mt++)
            #pragma unroll
            for (int nt = 0; nt < 2; nt++)
                #pragma unroll
                for (int r = 0; r < 4; r++) acc[mt][nt][r] = 0.0f;

        #pragma unroll
        for (int k = 0; k < 8; k++) {
            uint4 bh4 = W2fh4[(k * 8 + ng) * 32 + lane];
            uint4 bl4 = W2fl4[(k * 8 + ng) * 32 + lane];
            uint32_t ah[4][4], al[4][4];
            #pragma unroll
            for (int mt = 0; mt < 4; mt++) {
                ldsm_x4(ah[mt], aHi + aFragOff + mt * (16 * LDAB) + k * 32);
                ldsm_x4(al[mt], aLo + aFragOff + mt * (16 * LDAB) + k * 32);
            }
            #pragma unroll
            for (int mt = 0; mt < 4; mt++) {
                mma_bf16(acc[mt][0], ah[mt], bh4.x, bh4.y);
                mma_bf16(acc[mt][1], ah[mt], bh4.z, bh4.w);
            }
            #pragma unroll
            for (int mt = 0; mt < 4; mt++) {
                mma_bf16(acc[mt][0], ah[mt], bl4.x, bl4.y);
                mma_bf16(acc[mt][1], ah[mt], bl4.z, bl4.w);
            }
            #pragma unroll
            for (int mt = 0; mt < 4; mt++) {
                mma_bf16(acc[mt][0], al[mt], bh4.x, bh4.y);
                mma_bf16(acc[mt][1], al[mt], bh4.z, bh4.w);
            }
        }

        // ---- epilogue 2: per-row partial scores ----
        {
            const int ccol = (lane & 3) * 2;
            #pragma unroll
            for (int mt = 0; mt < 4; mt++) {
                float p0 = 0.0f, p1 = 0.0f;
                #pragma unroll
                for (int nt = 0; nt < 2; nt++) {
                    int c = ng * 16 + nt * 8 + ccol;
                    float bb0 = sBB[c], bb1 = sBB[c + 1];
                    float w30 = sW3[c], w31 = sW3[c + 1];
                    p0 += fmaxf(acc[mt][nt][0] + bb0, 0.0f) * w30
                        + fmaxf(acc[mt][nt][1] + bb1, 0.0f) * w31;
                    p1 += fmaxf(acc[mt][nt][2] + bb0, 0.0f) * w30
                        + fmaxf(acc[mt][nt][3] + bb1, 0.0f) * w31;
                }
                p0 += __shfl_xor_sync(0xffffffffu, p0, 1);
                p0 += __shfl_xor_sync(0xffffffffu, p0, 2);
                p1 += __shfl_xor_sync(0xffffffffu, p1, 1);
                p1 += __shfl_xor_sync(0xffffffffu, p1, 2);
                if ((lane & 3) == 0) {
                    int r = mt * 16 + (lane >> 2);
                    sRed[r * 8 + ng]       = p0;
                    sRed[(r + 8) * 8 + ng] = p1;
                }
            }
        }
        __syncthreads();   // A reads done (safe to restage); sRed visible

        if (t < 64) {
            float s8 = 0.0f;
            #pragma unroll
            for (int g = 0; g < 8; g++) s8 += sRed[t * 8 + g];
            sSc[l0 + t] = s8 + b3v;
        }
        // no sync needed here: sSc only read after a later barrier
    }
    __syncthreads();

    // ---- softmax over valid l ----
    int kli;
    if (g_len64) kli = (int)((const long long*)keys_length)[b];
    else         kli = ((const int*)keys_length)[b];
    kli = min(max(kli, 0), LK);

    float s = (t < kli) ? sSc[t] : -3.0e38f;
    float mw = s;
    #pragma unroll
    for (int off = 16; off > 0; off >>= 1)
        mw = fmaxf(mw, __shfl_down_sync(0xffffffffu, mw, off));
    if (lane == 0) sRed[w] = mw;
    __syncthreads();
    float m = sRed[0];
    #pragma unroll
    for (int ww = 1; ww < 8; ww++) m = fmaxf(m, sRed[ww]);

    float wgt = (t < kli) ? expf(s - m) : 0.0f;
    sSc[t] = wgt;
    float sw = wgt;
    #pragma unroll
    for (int off = 16; off > 0; off >>= 1)
        sw += __shfl_down_sync(0xffffffffu, sw, off);
    if (lane == 0) sRed[8 + w] = sw;
    __syncthreads();
    float tot = 0.0f;
    #pragma unroll
    for (int ww = 0; ww < 8; ww++) tot += sRed[8 + ww];
    const float inv = 1.0f / tot;
    __syncthreads();

    // ---- weighted sum of keys_p ----
    {
        int ei = t & 127, half = t >> 7;
        float acc2 = 0.0f;
        const float* kb = keys + (size_t)b * LK * EB;
        for (int l = half; l < kli; l += 2)
            acc2 += sSc[l] * (kb[l * EB + ei] + pos_emb[l * EB + ei]);
        sRed[t] = acc2;
        __syncthreads();
        if (t < 128)
            out[(size_t)b * EB + t] = (sRed[t] + sRed[t + 128]) * inv;
    }
}

extern "C" void kernel_launch(void* const* d_in, const int* in_sizes, int n_in,
                              void* d_out, int out_size) {
    const float* query       = (const float*)d_in[0];
    const float* keys        = (const float*)d_in[1];
    const void*  keys_length = d_in[2];
    const float* pos_emb     = (const float*)d_in[3];
    const float* W1          = (const float*)d_in[4];
    const float* b1          = (const float*)d_in[5];
    const float* W2          = (const float*)d_in[6];
    const float* b2          = (const float*)d_in[7];
    const float* W3          = (const float*)d_in[8];
    const float* b3          = (const float*)d_in[9];
    float* out = (float*)d_out;

    const int B = in_sizes[2];  // 4096

    static int attr_done = 0;
    if (!attr_done) {
        cudaFuncSetAttribute(prep_kernel, cudaFuncAttributeMaxDynamicSharedMemorySize, 16512 * 4);
        cudaFuncSetAttribute(din_kernel,  cudaFuncAttributeMaxDynamicSharedMemorySize, SMEM_BYTES);
        attr_done = 1;
    }

    prep_kernel<<<161, 256, 16512 * 4>>>(W1, b1, W2, query,
                                         (const unsigned int*)keys_length, B);
    din_kernel<<<4096, 256, SMEM_BYTES>>>(query, keys, keys_length, pos_emb,
                                          b2, W3, b3, out);
}

// round 8
// speedup vs baseline: 4.0096x; 1.0273x over previous
#include <cuda_runtime.h>
#include <cuda_bf16.h>
#include <cstdint>

// DIN sequence encoder, B=4096, L=200, E=A=128.
// Factorization: att_in@W1 = q@(W1a+W1c) + keys_p@[(W1b-W1c) + diag(q)*W1d]
// 256 threads/CTA, 2 CTAs/SM. 64-row l-tiles. mma.sync bf16 3-term split.
// 32x32 warp tiles + register-double-buffered (pipelined) k-loop.

#define EB 128
#define AB 128
#define LK 200
#define NB 4096
#define LDAE 136
#define LDAB (LDAE * 2)          // 272 B row stride

__device__ float g_W1kT[EB * AB];                    // [n][e] = (W1b - W1c)^T
__device__ float g_W1dT[EB * AB];                    // [n][e] = W1d^T
__device__ __align__(16) uint32_t g_W2fh[8192];      // W2 hi fragments (per-thread images)
__device__ __align__(16) uint32_t g_W2fl[8192];      // W2 lo fragments
__device__ float g_U[NB * AB];                       // u = q @ (W1a+W1c) + b1
__device__ int   g_len64;

__device__ __forceinline__ uint32_t packsplit(float x0, float x1, uint32_t& lop) {
    __nv_bfloat16 h0 = __float2bfloat16(x0);
    __nv_bfloat16 h1 = __float2bfloat16(x1);
    __nv_bfloat16 l0 = __float2bfloat16(x0 - __bfloat162float(h0));
    __nv_bfloat16 l1 = __float2bfloat16(x1 - __bfloat162float(h1));
    lop = ((uint32_t)__bfloat16_as_ushort(l1) << 16) | (uint32_t)__bfloat16_as_ushort(l0);
    return ((uint32_t)__bfloat16_as_ushort(h1) << 16) | (uint32_t)__bfloat16_as_ushort(h0);
}

// ---------------- prep kernel: grid 161 x 256 ----------------
__global__ void prep_kernel(const float* __restrict__ W1,
                            const float* __restrict__ b1,
                            const float* __restrict__ W2,
                            const float* __restrict__ query,
                            const unsigned int* __restrict__ kl_words, int B) {
    extern __shared__ float sp[];
    const int t = threadIdx.x;
    const int blk = blockIdx.x;

    if (blk < 64) {                       // W1 transposes (fp32)
        int i = blk * 256 + t;
        int e = i >> 7, n = i & 127;
        g_W1kT[n * EB + e] = W1[EB * AB + e * AB + n] - W1[2 * EB * AB + e * AB + n];
        g_W1dT[n * EB + e] = W1[3 * EB * AB + e * AB + n];
        return;
    }
    if (blk < 96) {                       // W2 fragment images for mma B operand
        int i = (blk - 64) * 256 + t;     // 0..8191
        // i = ((s*8+ng)*32 + lane)*4 + j ; ng = 16-col group
        int j = i & 3, lane = (i >> 2) & 31, ng = (i >> 7) & 7, s = i >> 10;
        int n  = ng * 16 + ((j >> 1) << 3) + (lane >> 2);
        int k0 = s * 16 + (lane & 3) * 2 + ((j & 1) ? 8 : 0);
        float a = W2[k0 * AB + n];
        float bv = W2[(k0 + 1) * AB + n];
        uint32_t lop, hip = packsplit(a, bv, lop);
        g_W2fh[i] = hip;
        g_W2fl[i] = lop;
        return;
    }
    if (blk == 96) {                      // keys_length dtype sniffer
        int local = 0;
        for (int i = t; i < B / 2; i += 256)
            if (kl_words[2 * i + 1] != 0u) local = 1;
        int any = __syncthreads_or(local);
        if (t == 0) g_len64 = any ? 0 : 1;
        return;
    }

    // g_U blocks (97..160)
    float* sW = sp;            // 16384: W1a + W1c
    float* sq = sp + 16384;    // 128
    for (int i = t; i < EB * AB; i += 256)
        sW[i] = W1[i] + W1[2 * EB * AB + i];
    __syncthreads();
    int bid2 = blk - 97;
    for (int bb2 = 0; bb2 < 64; bb2++) {
        int bb = bid2 * 64 + bb2;
        if (t < 128) sq[t] = query[(size_t)bb * EB + t];
        __syncthreads();
        if (t < 128) {
            float acc = b1[t];
            #pragma unroll 8
            for (int e = 0; e < EB; e++) acc += sq[e] * sW[e * AB + t];
            g_U[(size_t)bb * AB + t] = acc;
        }
        __syncthreads();
    }
}

// ---------------- MMA helpers ----------------
__device__ __forceinline__ uint32_t smem_u32(const void* p) {
    uint32_t a;
    asm("{ .reg .u64 tmp; cvta.to.shared.u64 tmp, %1; cvt.u32.u64 %0, tmp; }"
        : "=r"(a) : "l"(p));
    return a;
}
__device__ __forceinline__ void ldsm_x4(uint32_t* r, uint32_t addr) {
    asm volatile("ldmatrix.sync.aligned.m8n8.x4.shared.b16 {%0,%1,%2,%3}, [%4];"
                 : "=r"(r[0]), "=r"(r[1]), "=r"(r[2]), "=r"(r[3]) : "r"(addr));
}
__device__ __forceinline__ void mma_bf16(float* d, const uint32_t* a,
                                         uint32_t b0, uint32_t b1) {
    asm volatile("mma.sync.aligned.m16n8k16.row.col.f32.bf16.bf16.f32 "
                 "{%0,%1,%2,%3},{%4,%5,%6,%7},{%8,%9},{%0,%1,%2,%3};"
                 : "+f"(d[0]), "+f"(d[1]), "+f"(d[2]), "+f"(d[3])
                 : "r"(a[0]), "r"(a[1]), "r"(a[2]), "r"(a[3]), "r"(b0), "r"(b1));
}

// ---------------- SMEM layout (bytes) ----------------
#define OFF_AHI  0                        // 64*272 = 17408
#define OFF_ALO  17408
#define OFF_B1HI 34816                    // 128*272 = 34816
#define OFF_B1LO 69632
#define OFF_Q    104448
#define OFF_U    104960
#define OFF_BB2  105472
#define OFF_W3   105984
#define OFF_SC   106496                   // 256 floats
#define OFF_RED  107520                   // 512 floats
#define SMEM_BYTES 109568

__global__ void __launch_bounds__(256, 2) din_kernel(
    const float* __restrict__ query,
    const float* __restrict__ keys,
    const void*  __restrict__ keys_length,
    const float* __restrict__ pos_emb,
    const float* __restrict__ b2,
    const float* __restrict__ W3,
    const float* __restrict__ b3,
    float* __restrict__ out)
{
    extern __shared__ char smc[];
    float* sQ   = (float*)(smc + OFF_Q);
    float* sU   = (float*)(smc + OFF_U);
    float* sBB  = (float*)(smc + OFF_BB2);
    float* sW3  = (float*)(smc + OFF_W3);
    float* sSc  = (float*)(smc + OFF_SC);
    float* sRed = (float*)(smc + OFF_RED);

    const int b = blockIdx.x;
    const int t = threadIdx.x;
    const int w = t >> 5, lane = t & 31;

    if (t < 128) {
        sQ[t]  = query[(size_t)b * EB + t];
        sU[t]  = g_U[(size_t)b * AB + t];
        sBB[t] = b2[t];
        sW3[t] = W3[t];
    }
    __syncthreads();
    const float b3v = b3[0];

    // ---- stage B1 = WbT hi/lo (q-dependent) ----
    {
        uint32_t* hi = (uint32_t*)(smc + OFF_B1HI);
        uint32_t* lo = (uint32_t*)(smc + OFF_B1LO);
        #pragma unroll 4
        for (int i = t; i < 8192; i += 256) {
            int n = i >> 6, e2 = (i & 63) * 2;
            float x0 = g_W1kT[n * EB + e2]     + sQ[e2]     * g_W1dT[n * EB + e2];
            float x1 = g_W1kT[n * EB + e2 + 1] + sQ[e2 + 1] * g_W1dT[n * EB + e2 + 1];
            uint32_t lop, hip = packsplit(x0, x1, lop);
            uint32_t wi = n * 68 + (i & 63);
            hi[wi] = hip;
            lo[wi] = lop;
        }
    }

    const uint32_t aHi  = smem_u32(smc + OFF_AHI);
    const uint32_t aLo  = smem_u32(smc + OFF_ALO);
    const uint32_t b1Hi = smem_u32(smc + OFF_B1HI);
    const uint32_t b1Lo = smem_u32(smc + OFF_B1LO);

    // 32x32 warp tiles: 2 m-groups x 4 n-groups
    const int wm = w >> 2, wn = w & 3;
    const int m0 = wm * 32, n0 = wn * 32;
    const uint32_t lrow  = (((lane >> 3) & 1) << 3) + (lane & 7);
    const uint32_t lcolb = (lane >> 4) << 4;
    const uint32_t aOff  = (m0 + lrow) * LDAB + lcolb;
    const uint32_t bOff  = (n0 + lrow) * LDAB + lcolb;

    const uint4* W2fh4 = (const uint4*)g_W2fh;
    const uint4* W2fl4 = (const uint4*)g_W2fl;
    const int ng0 = wn * 2, ng1 = wn * 2 + 1;

    for (int tile = 0; tile < 4; tile++) {
        const int l0 = tile * 64;

        // ---- stage A = keys_p tile (64 rows), hi/lo split ----
        {
            uint32_t* hi = (uint32_t*)(smc + OFF_AHI);
            uint32_t* lo = (uint32_t*)(smc + OFF_ALO);
            #pragma unroll 4
            for (int i = t; i < 4096; i += 256) {
                int l = i >> 6, e2 = (i & 63) * 2;
                int gl = l0 + l;
                float x0 = 0.0f, x1 = 0.0f;
                if (gl < LK) {
                    float2 kv = *(const float2*)(keys + ((size_t)b * LK + gl) * EB + e2);
                    float2 pv = *(const float2*)(pos_emb + (size_t)gl * EB + e2);
                    x0 = kv.x + pv.x; x1 = kv.y + pv.y;
                }
                uint32_t lop, hip = packsplit(x0, x1, lop);
                uint32_t wi = l * 68 + (i & 63);
                hi[wi] = hip;
                lo[wi] = lop;
            }
        }
        __syncthreads();

        float acc[2][4][4];
        #pragma unroll
        for (int mt = 0; mt < 2; mt++)
            #pragma unroll
            for (int nt = 0; nt < 4; nt++)
                #pragma unroll
                for (int r = 0; r < 4; r++) acc[mt][nt][r] = 0.0f;

        // ---- layer 1 GEMM, pipelined (register double buffer) ----
        {
            uint32_t ah[2][2][4], al[2][2][4], bh[2][8], bl[2][8];
            #define LOAD1(buf, kk) do { \
                ldsm_x4(ah[buf][0], aHi + aOff + (kk) * 32); \
                ldsm_x4(ah[buf][1], aHi + aOff + 16 * LDAB + (kk) * 32); \
                ldsm_x4(al[buf][0], aLo + aOff + (kk) * 32); \
                ldsm_x4(al[buf][1], aLo + aOff + 16 * LDAB + (kk) * 32); \
                ldsm_x4(bh[buf],     b1Hi + bOff + (kk) * 32); \
                ldsm_x4(bh[buf] + 4, b1Hi + bOff + 16 * LDAB + (kk) * 32); \
                ldsm_x4(bl[buf],     b1Lo + bOff + (kk) * 32); \
                ldsm_x4(bl[buf] + 4, b1Lo + bOff + 16 * LDAB + (kk) * 32); \
            } while (0)
            LOAD1(0, 0);
            #pragma unroll
            for (int k = 0; k < 8; k++) {
                const int cb = k & 1, nb = cb ^ 1;
                if (k < 7) LOAD1(nb, k + 1);
                #pragma unroll
                for (int mt = 0; mt < 2; mt++) {
                    mma_bf16(acc[mt][0], ah[cb][mt], bh[cb][0], bh[cb][2]);
                    mma_bf16(acc[mt][1], ah[cb][mt], bh[cb][1], bh[cb][3]);
                    mma_bf16(acc[mt][2], ah[cb][mt], bh[cb][4], bh[cb][6]);
                    mma_bf16(acc[mt][3], ah[cb][mt], bh[cb][5], bh[cb][7]);
                }
                #pragma unroll
                for (int mt = 0; mt < 2; mt++) {
                    mma_bf16(acc[mt][0], ah[cb][mt], bl[cb][0], bl[cb][2]);
                    mma_bf16(acc[mt][1], ah[cb][mt], bl[cb][1], bl[cb][3]);
                    mma_bf16(acc[mt][2], ah[cb][mt], bl[cb][4], bl[cb][6]);
                    mma_bf16(acc[mt][3], ah[cb][mt], bl[cb][5], bl[cb][7]);
                }
                #pragma unroll
                for (int mt = 0; mt < 2; mt++) {
                    mma_bf16(acc[mt][0], al[cb][mt], bh[cb][0], bh[cb][2]);
                    mma_bf16(acc[mt][1], al[cb][mt], bh[cb][1], bh[cb][3]);
                    mma_bf16(acc[mt][2], al[cb][mt], bh[cb][4], bh[cb][6]);
                    mma_bf16(acc[mt][3], al[cb][mt], bh[cb][5], bh[cb][7]);
                }
            }
            #undef LOAD1
        }
        __syncthreads();   // A reads done -> safe to overwrite with H1

        // ---- epilogue 1: H1 = relu(z1 + u) -> A buffers ----
        {
            uint32_t* hi = (uint32_t*)(smc + OFF_AHI);
            uint32_t* lo = (uint32_t*)(smc + OFF_ALO);
            const int rrow = lane >> 2;
            const int ccol = (lane & 3) * 2;
            #pragma unroll
            for (int mt = 0; mt < 2; mt++) {
                #pragma unroll
                for (int nt = 0; nt < 4; nt++) {
                    int c = n0 + nt * 8 + ccol;
                    float u0 = sU[c], u1 = sU[c + 1];
                    int r0 = m0 + mt * 16 + rrow;
                    float h0 = fmaxf(acc[mt][nt][0] + u0, 0.0f);
                    float h1 = fmaxf(acc[mt][nt][1] + u1, 0.0f);
                    uint32_t lop, hip = packsplit(h0, h1, lop);
                    uint32_t wi = r0 * 68 + (c >> 1);
                    hi[wi] = hip; lo[wi] = lop;
                    h0 = fmaxf(acc[mt][nt][2] + u0, 0.0f);
                    h1 = fmaxf(acc[mt][nt][3] + u1, 0.0f);
                    hip = packsplit(h0, h1, lop);
                    wi = (r0 + 8) * 68 + (c >> 1);
                    hi[wi] = hip; lo[wi] = lop;
                }
            }
        }
        __syncthreads();

        // ---- layer 2 GEMM: B = W2 fragments from gmem, pipelined ----
        #pragma unroll
        for (int mt = 0; mt < 2; mt++)
            #pragma unroll
            for (int nt = 0; nt < 4; nt++)
                #pragma unroll
                for (int r = 0; r < 4; r++) acc[mt][nt][r] = 0.0f;

        {
            uint32_t ah[2][2][4], al[2][2][4];
            uint4 b2h[2][2], b2l[2][2];
            #define LOAD2(buf, kk) do { \
                ldsm_x4(ah[buf][0], aHi + aOff + (kk) * 32); \
                ldsm_x4(ah[buf][1], aHi + aOff + 16 * LDAB + (kk) * 32); \
                ldsm_x4(al[buf][0], aLo + aOff + (kk) * 32); \
                ldsm_x4(al[buf][1], aLo + aOff + 16 * LDAB + (kk) * 32); \
                b2h[buf][0] = W2fh4[((kk) * 8 + ng0) * 32 + lane]; \
                b2h[buf][1] = W2fh4[((kk) * 8 + ng1) * 32 + lane]; \
                b2l[buf][0] = W2fl4[((kk) * 8 + ng0) * 32 + lane]; \
                b2l[buf][1] = W2fl4[((kk) * 8 + ng1) * 32 + lane]; \
            } while (0)
            LOAD2(0, 0);
            #pragma unroll
            for (int k = 0; k < 8; k++) {
                const int cb = k & 1, nb = cb ^ 1;
                if (k < 7) LOAD2(nb, k + 1);
                #pragma unroll
                for (int mt = 0; mt < 2; mt++) {
                    mma_bf16(acc[mt][0], ah[cb][mt], b2h[cb][0].x, b2h[cb][0].y);
                    mma_bf16(acc[mt][1], ah[cb][mt], b2h[cb][0].z, b2h[cb][0].w);
                    mma_bf16(acc[mt][2], ah[cb][mt], b2h[cb][1].x, b2h[cb][1].y);
                    mma_bf16(acc[mt][3], ah[cb][mt], b2h[cb][1].z, b2h[cb][1].w);
                }
                #pragma unroll
                for (int mt = 0; mt < 2; mt++) {
                    mma_bf16(acc[mt][0], ah[cb][mt], b2l[cb][0].x, b2l[cb][0].y);
                    mma_bf16(acc[mt][1], ah[cb][mt], b2l[cb][0].z, b2l[cb][0].w);
                    mma_bf16(acc[mt][2], ah[cb][mt], b2l[cb][1].x, b2l[cb][1].y);
                    mma_bf16(acc[mt][3], ah[cb][mt], b2l[cb][1].z, b2l[cb][1].w);
                }
                #pragma unroll
                for (int mt = 0; mt < 2; mt++) {
                    mma_bf16(acc[mt][0], al[cb][mt], b2h[cb][0].x, b2h[cb][0].y);
                    mma_bf16(acc[mt][1], al[cb][mt], b2h[cb][0].z, b2h[cb][0].w);
                    mma_bf16(acc[mt][2], al[cb][mt], b2h[cb][1].x, b2h[cb][1].y);
                    mma_bf16(acc[mt][3], al[cb][mt], b2h[cb][1].z, b2h[cb][1].w);
                }
            }
            #undef LOAD2
        }

        // ---- epilogue 2: per-row partial scores ----
        {
            const int ccol = (lane & 3) * 2;
            #pragma unroll
            for (int mt = 0; mt < 2; mt++) {
                float p0 = 0.0f, p1 = 0.0f;
                #pragma unroll
                for (int nt = 0; nt < 4; nt++) {
                    int c = n0 + nt * 8 + ccol;
                    float bb0 = sBB[c], bb1 = sBB[c + 1];
                    float w30 = sW3[c], w31 = sW3[c + 1];
                    p0 += fmaxf(acc[mt][nt][0] + bb0, 0.0f) * w30
                        + fmaxf(acc[mt][nt][1] + bb1, 0.0f) * w31;
                    p1 += fmaxf(acc[mt][nt][2] + bb0, 0.0f) * w30
                        + fmaxf(acc[mt][nt][3] + bb1, 0.0f) * w31;
                }
                p0 += __shfl_xor_sync(0xffffffffu, p0, 1);
                p0 += __shfl_xor_sync(0xffffffffu, p0, 2);
                p1 += __shfl_xor_sync(0xffffffffu, p1, 1);
                p1 += __shfl_xor_sync(0xffffffffu, p1, 2);
                if ((lane & 3) == 0) {
                    int r = m0 + mt * 16 + (lane >> 2);
                    sRed[r * 4 + wn]       = p0;
                    sRed[(r + 8) * 4 + wn] = p1;
                }
            }
        }
        __syncthreads();

        if (t < 64) {
            float s4 = sRed[t * 4] + sRed[t * 4 + 1] + sRed[t * 4 + 2] + sRed[t * 4 + 3];
            sSc[l0 + t] = s4 + b3v;
        }
    }
    __syncthreads();

    // ---- softmax over valid l ----
    int kli;
    if (g_len64) kli = (int)((const long long*)keys_length)[b];
    else         kli = ((const int*)keys_length)[b];
    kli = min(max(kli, 0), LK);

    float s = (t < kli) ? sSc[t] : -3.0e38f;
    float mw = s;
    #pragma unroll
    for (int off = 16; off > 0; off >>= 1)
        mw = fmaxf(mw, __shfl_down_sync(0xffffffffu, mw, off));
    if (lane == 0) sRed[w] = mw;
    __syncthreads();
    float m = sRed[0];
    #pragma unroll
    for (int ww = 1; ww < 8; ww++) m = fmaxf(m, sRed[ww]);

    float wgt = (t < kli) ? expf(s - m) : 0.0f;
    sSc[t] = wgt;
    float sw = wgt;
    #pragma unroll
    for (int off = 16; off > 0; off >>= 1)
        sw += __shfl_down_sync(0xffffffffu, sw, off);
    if (lane == 0) sRed[8 + w] = sw;
    __syncthreads();
    float tot = 0.0f;
    #pragma unroll
    for (int ww = 0; ww < 8; ww++) tot += sRed[8 + ww];
    const float inv = 1.0f / tot;
    __syncthreads();

    // ---- weighted sum of keys_p ----
    {
        int ei = t & 127, half = t >> 7;
        float acc2 = 0.0f;
        const float* kb = keys + (size_t)b * LK * EB;
        for (int l = half; l < kli; l += 2)
            acc2 += sSc[l] * (kb[l * EB + ei] + pos_emb[l * EB + ei]);
        sRed[t] = acc2;
        __syncthreads();
        if (t < 128)
            out[(size_t)b * EB + t] = (sRed[t] + sRed[t + 128]) * inv;
    }
}

extern "C" void kernel_launch(void* const* d_in, const int* in_sizes, int n_in,
                              void* d_out, int out_size) {
    const float* query       = (const float*)d_in[0];
    const float* keys        = (const float*)d_in[1];
    const void*  keys_length = d_in[2];
    const float* pos_emb     = (const float*)d_in[3];
    const float* W1          = (const float*)d_in[4];
    const float* b1          = (const float*)d_in[5];
    const float* W2          = (const float*)d_in[6];
    const float* b2          = (const float*)d_in[7];
    const float* W3          = (const float*)d_in[8];
    const float* b3          = (const float*)d_in[9];
    float* out = (float*)d_out;

    const int B = in_sizes[2];  // 4096

    static int attr_done = 0;
    if (!attr_done) {
        cudaFuncSetAttribute(prep_kernel, cudaFuncAttributeMaxDynamicSharedMemorySize, 16512 * 4);
        cudaFuncSetAttribute(din_kernel,  cudaFuncAttributeMaxDynamicSharedMemorySize, SMEM_BYTES);
        attr_done = 1;
    }

    prep_kernel<<<161, 256, 16512 * 4>>>(W1, b1, W2, query,
                                         (const unsigned int*)keys_length, B);
    din_kernel<<<4096, 256, SMEM_BYTES>>>(query, keys, keys_length, pos_emb,
                                          b2, W3, b3, out);
}